// round 14
// baseline (speedup 1.0000x reference)
#include <cuda_runtime.h>
#include <cuda_bf16.h>
#include <cstdint>

// Problem constants
#define BATCH 16
#define SEQ   1024
#define T     (BATCH * SEQ)      // 16384 serial steps
#define HID   600
#define IN    512                // 3 (tag emb) + 509 (context)
#define G3    1800               // 3*HID

// Recurrence config: two independent 60-block chains (fwd / bwd),
// 10 warps per block, each warp owns ONE hidden output of its chain.
#define CBLK  60                 // blocks per chain
#define NBLK  (2 * CBLK)         // total persistent blocks
#define IPB   10                 // hidden indices per block (CBLK*IPB = 600)
#define RTHREADS 320             // 10 warps
#define H4    160                // 640 floats = 160 float4 per h buffer
#define NMIR  4                  // epoch mirror lines per chain

// ------------------- static device scratch (no allocations allowed) -------
__device__ float    d_X[(size_t)T * IN];        // 33.5 MB  built input
__device__ float    d_gx[(size_t)T * G3];       // 118 MB   precomputed gates
__device__ __align__(16) float d_h[2][2][640];  // [dir][parity][slot]
__device__ unsigned d_count[2][32];             // per-chain counter: REDs + 1 reader
__device__ unsigned d_ep[2][NMIR * 32];         // per-chain epoch mirrors, 128B apart

// ------------------- memory-order helpers ---------------------------------
__device__ __forceinline__ unsigned ld_rlx(const unsigned* p) {
    unsigned v;
    asm volatile("ld.relaxed.gpu.global.b32 %0, [%1];" : "=r"(v) : "l"(p) : "memory");
    return v;
}
__device__ __forceinline__ void st_rel(unsigned* p, unsigned v) {
    asm volatile("st.global.release.gpu.b32 [%0], %1;" :: "l"(p), "r"(v) : "memory");
}
// release-decorated fire-and-forget arrival (no MEMBAR, no blocking)
__device__ __forceinline__ void red_rel_add(unsigned* p, unsigned v) {
    asm volatile("red.release.gpu.global.add.u32 [%0], %1;" :: "l"(p), "r"(v) : "memory");
}
__device__ __forceinline__ void fence_ar_gpu() {
    asm volatile("fence.acq_rel.gpu;" ::: "memory");
}
__device__ __forceinline__ float sigm(float x) {
    return 1.0f / (1.0f + __expf(-x));
}
__device__ __forceinline__ float tanh_fast(float x) {
    x = fminf(15.0f, fmaxf(-15.0f, x));
    float e = __expf(2.0f * x);
    return __fdividef(e - 1.0f, e + 1.0f);
}

// ------------------- kernel 0: init barrier + h buffers -------------------
__global__ void init_bufs() {
    int t = threadIdx.x + blockIdx.x * blockDim.x;
    float* h = (float*)d_h;
    if (t < 2 * 2 * 640) h[t] = 0.0f;
    if (t < 2) d_count[t][0] = 0u;
    if (t < 2 * NMIR) d_ep[t / NMIR][(t % NMIR) * 32] = 0u;
}

// ------------------- kernel 1: build X = [tag_emb(tags), context] ---------
__global__ void build_x(const float* __restrict__ ctx,
                        const int* __restrict__ tags,
                        const float* __restrict__ emb) {
    int t = blockIdx.x;        // 0..16383
    int k = threadIdx.x;       // 0..511
    float v;
    if (k < 3) v = emb[tags[t] * 3 + k];
    else       v = ctx[(size_t)t * 509 + (k - 3)];
    d_X[(size_t)t * IN + k] = v;
}

// ------------------- kernel 2: gx = X @ W_ih^T + b_ih ---------------------
#define BM 128
#define BN 128
#define BKK 16
__global__ __launch_bounds__(256) void gemm_gx(const float* __restrict__ Wih,
                                               const float* __restrict__ bih) {
    __shared__ float As[BKK][BM];
    __shared__ float Bs[BKK][BN];
    int tid = threadIdx.x;
    int bm = blockIdx.x * BM;
    int bn = blockIdx.y * BN;
    int tx = tid & 15;
    int ty = tid >> 4;
    float acc[8][8];
#pragma unroll
    for (int r = 0; r < 8; r++)
#pragma unroll
        for (int c = 0; c < 8; c++) acc[r][c] = 0.0f;

    for (int k0 = 0; k0 < IN; k0 += BKK) {
#pragma unroll
        for (int i = 0; i < 2; i++) {
            int id = tid + i * 256;
            int m  = id >> 2;
            int kq = (id & 3) * 4;
            float4 v = *(const float4*)&d_X[(size_t)(bm + m) * IN + k0 + kq];
            As[kq + 0][m] = v.x; As[kq + 1][m] = v.y;
            As[kq + 2][m] = v.z; As[kq + 3][m] = v.w;
        }
#pragma unroll
        for (int i = 0; i < 2; i++) {
            int id = tid + i * 256;
            int n  = id >> 2;
            int kq = (id & 3) * 4;
            int j  = bn + n;
            float4 v = make_float4(0.f, 0.f, 0.f, 0.f);
            if (j < G3) v = *(const float4*)&Wih[(size_t)j * IN + k0 + kq];
            Bs[kq + 0][n] = v.x; Bs[kq + 1][n] = v.y;
            Bs[kq + 2][n] = v.z; Bs[kq + 3][n] = v.w;
        }
        __syncthreads();
#pragma unroll
        for (int kk = 0; kk < BKK; kk++) {
            float a[8], b[8];
#pragma unroll
            for (int u = 0; u < 4; u++) {
                a[u]     = As[kk][ty * 4 + u];
                a[4 + u] = As[kk][64 + ty * 4 + u];
                b[u]     = Bs[kk][tx * 4 + u];
                b[4 + u] = Bs[kk][64 + tx * 4 + u];
            }
#pragma unroll
            for (int r = 0; r < 8; r++)
#pragma unroll
                for (int c = 0; c < 8; c++) acc[r][c] += a[r] * b[c];
        }
        __syncthreads();
    }
#pragma unroll
    for (int r = 0; r < 8; r++) {
        int m = bm + ((r < 4) ? (ty * 4 + r) : (64 + ty * 4 + (r - 4)));
#pragma unroll
        for (int c = 0; c < 8; c++) {
            int j = bn + ((c < 4) ? (tx * 4 + c) : (64 + tx * 4 + (c - 4)));
            if (j < G3)
                d_gx[(size_t)m * G3 + j] = acc[r][c] + __ldg(&bih[j]);
        }
    }
}

// ------------------- kernel 3: persistent bidirectional GRU recurrence ----
// Two independent 60-block chains (blocks [0,60) = fwd, [60,120) = bwd).
// Barrier per chain: release-REDG arrivals on the chain counter (writers
// only); ONE observer (chain block 0) relaxed-polls the counter and relays
// the epoch to 4 mirrored lines; other blocks relaxed-poll their mirror.
// Separates the atomic write-line from the poll read-lines.
__global__ void __launch_bounds__(RTHREADS, 1)
gru_recur(const float* __restrict__ Whh,
          const float* __restrict__ bhh,
          float* __restrict__ out) {
    __shared__ __align__(16) float s_h[640];

    int tid  = threadIdx.x;
    int w    = tid >> 5;
    int lane = tid & 31;
    int dir  = (blockIdx.x < CBLK) ? 0 : 1;     // 0 = fwd, 1 = bwd
    int blkl = blockIdx.x - dir * CBLK;
    int i    = blkl * IPB + w;                  // this warp's hidden index
    unsigned* cnt = &d_count[dir][0];
    unsigned* ep  = &d_ep[dir][(blkl & (NMIR - 1)) * 32];

    // --- load this warp's W_hh rows into registers (zero-padded) ---
    float wr[20], wz[20], wn[20];
#pragma unroll
    for (int c = 0; c < 5; c++) {
#pragma unroll
        for (int u = 0; u < 4; u++) {
            int k = c * 128 + lane * 4 + u;
            bool ok = (k < HID);
            wr[c * 4 + u] = ok ? Whh[(size_t)(0 * HID + i) * HID + k] : 0.0f;
            wz[c * 4 + u] = ok ? Whh[(size_t)(1 * HID + i) * HID + k] : 0.0f;
            wn[c * 4 + u] = ok ? Whh[(size_t)(2 * HID + i) * HID + k] : 0.0f;
        }
    }
    float bhr = 0.f, bhz = 0.f, bhn = 0.f;
    if (lane == 0) {
        bhr = bhh[i];
        bhz = bhh[HID + i];
        bhn = bhh[2 * HID + i];
    }

    // --- prefetch gx for step 0 (fwd row 0 / bwd row 1023) ---
    float pg0 = 0.f, pg1 = 0.f, pg2 = 0.f;
    if (lane == 0) {
        const float* g = dir ? &d_gx[(size_t)1023 * G3] : &d_gx[(size_t)0 * G3];
        pg0 = __ldcg(g + i); pg1 = __ldcg(g + HID + i); pg2 = __ldcg(g + 2 * HID + i);
    }

    for (int s = 0; s < T; s++) {
        // ---- stage this direction's h into SMEM (160 float4) ----
        if (tid < H4) {
            const float4* h4 = (const float4*)d_h[dir][s & 1];
            ((float4*)s_h)[tid] = __ldcg(&h4[tid]);
        }

        // lane 0: consume this step's gates, prefetch step s+1
        float g0 = pg0, g1 = pg1, g2 = pg2;
        if (lane == 0 && s + 1 < T) {
            int sn  = s + 1;
            int row = dir ? (sn + 1023 - 2 * (sn & 1023)) : sn;
            const float* g = &d_gx[(size_t)row * G3];
            pg0 = __ldcg(g + i); pg1 = __ldcg(g + HID + i); pg2 = __ldcg(g + 2 * HID + i);
        }

        __syncthreads();

        // ---- dot products from SMEM ----
        float a = 0.f, z = 0.f, n = 0.f;
#pragma unroll
        for (int c = 0; c < 5; c++) {
            float4 hv = *(const float4*)&s_h[c * 128 + lane * 4];
            const float* WR = &wr[c * 4];
            const float* WZ = &wz[c * 4];
            const float* WN = &wn[c * 4];
            a += WR[0] * hv.x + WR[1] * hv.y + WR[2] * hv.z + WR[3] * hv.w;
            z += WZ[0] * hv.x + WZ[1] * hv.y + WZ[2] * hv.z + WZ[3] * hv.w;
            n += WN[0] * hv.x + WN[1] * hv.y + WN[2] * hv.z + WN[3] * hv.w;
        }
#pragma unroll
        for (int o = 16; o; o >>= 1) {
            a += __shfl_down_sync(0xffffffffu, a, o);
            z += __shfl_down_sync(0xffffffffu, z, o);
            n += __shfl_down_sync(0xffffffffu, n, o);
        }

        if (lane == 0) {
            float hi = s_h[i];
            float r_ = sigm(g0 + a + bhr);
            float z_ = sigm(g1 + z + bhz);
            float n_ = tanh_fast(g2 + r_ * (n + bhn));
            float hn = (1.0f - z_) * n_ + z_ * hi;
            d_h[dir][(s + 1) & 1][i] = hn;
            if (s == T - 1) out[dir * HID + i] = hn;
        }

        // ---- per-chain barrier: release-RED arrival + observer epoch relay
        if (s + 1 < T) {
            unsigned e = (unsigned)(s + 1);
            __syncthreads();                 // CTA h stores happen-before tid0
            if (tid == 0) {
                red_rel_add(cnt, 1u);        // release arrival (fire-and-forget)
                if (blkl == 0) {
                    // chain observer: sole reader of the counter line
                    unsigned tgt = e * CBLK;
                    while (ld_rlx(cnt) < tgt) { }
                    fence_ar_gpu();          // acquire arrivals' h stores
#pragma unroll
                    for (int m = 0; m < NMIR; m++)
                        st_rel(&d_ep[dir][m * 32], e);   // relay epoch
                } else {
                    while (ld_rlx(ep) < e) { }
                    fence_ar_gpu();          // acquire relayed h stores
                }
            }
            __syncthreads();
        }
    }
}

// ------------------- launch ------------------------------------------------
extern "C" void kernel_launch(void* const* d_in, const int* in_sizes, int n_in,
                              void* d_out, int out_size) {
    const float* context = (const float*)d_in[0];   // [16,1024,509]
    const int*   tags    = (const int*)  d_in[1];   // [16,1024]
    const float* tag_emb = (const float*)d_in[2];   // [3,3]
    const float* W_ih    = (const float*)d_in[3];   // [1800,512]
    const float* W_hh    = (const float*)d_in[4];   // [1800,600]
    const float* b_ih    = (const float*)d_in[5];   // [1800]
    const float* b_hh    = (const float*)d_in[6];   // [1800]
    float*       out     = (float*)d_out;           // [1200]

    init_bufs<<<4, 640>>>();
    build_x<<<T, IN>>>(context, tags, tag_emb);
    dim3 g((T + BM - 1) / BM, (G3 + BN - 1) / BN);  // 128 x 15
    gemm_gx<<<g, 256>>>(W_ih, b_ih);
    gru_recur<<<NBLK, RTHREADS>>>(W_hh, b_hh, out);
}

// round 15
// speedup vs baseline: 1.9845x; 1.9845x over previous
#include <cuda_runtime.h>
#include <cuda_bf16.h>
#include <cstdint>

// Problem constants
#define BATCH 16
#define SEQ   1024
#define T     (BATCH * SEQ)      // 16384 serial steps per chain
#define HID   600
#define IN    512                // 3 (tag emb) + 509 (context)
#define G3    1800               // 3*HID

// Recurrence config: 2 groups x 60 blocks. Each group covers ALL 600 hidden
// indices and alternates chains each phase (latency hiding across chains).
#define GBLK  60                 // blocks per group (= arrivals per chain-step)
#define NBLK  (2 * GBLK)         // total persistent blocks
#define IPB   10                 // hidden indices per block (GBLK*IPB = 600)
#define RTHREADS 320             // 10 warps, one hidden index each
#define H4    160                // 640 floats = 160 float4 per h buffer

// ------------------- static device scratch (no allocations allowed) -------
__device__ float    d_X[(size_t)T * IN];        // 33.5 MB  built input
__device__ float    d_gx[(size_t)T * G3];       // 118 MB   precomputed gates
__device__ __align__(16) float d_h[2][2][640];  // [chain][parity][slot]
__device__ unsigned d_count[2][32];             // per-chain arrival counter

// ------------------- memory-order helpers (r13 frozen barrier) -------------
__device__ __forceinline__ unsigned ld_rlx(const unsigned* p) {
    unsigned v;
    asm volatile("ld.relaxed.gpu.global.b32 %0, [%1];" : "=r"(v) : "l"(p) : "memory");
    return v;
}
__device__ __forceinline__ void red_rel_add(unsigned* p, unsigned v) {
    asm volatile("red.release.gpu.global.add.u32 [%0], %1;" :: "l"(p), "r"(v) : "memory");
}
__device__ __forceinline__ void fence_ar_gpu() {
    asm volatile("fence.acq_rel.gpu;" ::: "memory");
}
__device__ __forceinline__ float sigm(float x) {
    return 1.0f / (1.0f + __expf(-x));
}
__device__ __forceinline__ float tanh_fast(float x) {
    x = fminf(15.0f, fmaxf(-15.0f, x));
    float e = __expf(2.0f * x);
    return __fdividef(e - 1.0f, e + 1.0f);
}

// ------------------- kernel 0: init barrier + h buffers -------------------
__global__ void init_bufs() {
    int t = threadIdx.x + blockIdx.x * blockDim.x;
    float* h = (float*)d_h;
    if (t < 2 * 2 * 640) h[t] = 0.0f;
    if (t < 2) d_count[t][0] = 0u;
}

// ------------------- kernel 1: build X = [tag_emb(tags), context] ---------
__global__ void build_x(const float* __restrict__ ctx,
                        const int* __restrict__ tags,
                        const float* __restrict__ emb) {
    int t = blockIdx.x;        // 0..16383
    int k = threadIdx.x;       // 0..511
    float v;
    if (k < 3) v = emb[tags[t] * 3 + k];
    else       v = ctx[(size_t)t * 509 + (k - 3)];
    d_X[(size_t)t * IN + k] = v;
}

// ------------------- kernel 2: gx = X @ W_ih^T + b_ih ---------------------
#define BM 128
#define BN 128
#define BKK 16
__global__ __launch_bounds__(256) void gemm_gx(const float* __restrict__ Wih,
                                               const float* __restrict__ bih) {
    __shared__ float As[BKK][BM];
    __shared__ float Bs[BKK][BN];
    int tid = threadIdx.x;
    int bm = blockIdx.x * BM;
    int bn = blockIdx.y * BN;
    int tx = tid & 15;
    int ty = tid >> 4;
    float acc[8][8];
#pragma unroll
    for (int r = 0; r < 8; r++)
#pragma unroll
        for (int c = 0; c < 8; c++) acc[r][c] = 0.0f;

    for (int k0 = 0; k0 < IN; k0 += BKK) {
#pragma unroll
        for (int i = 0; i < 2; i++) {
            int id = tid + i * 256;
            int m  = id >> 2;
            int kq = (id & 3) * 4;
            float4 v = *(const float4*)&d_X[(size_t)(bm + m) * IN + k0 + kq];
            As[kq + 0][m] = v.x; As[kq + 1][m] = v.y;
            As[kq + 2][m] = v.z; As[kq + 3][m] = v.w;
        }
#pragma unroll
        for (int i = 0; i < 2; i++) {
            int id = tid + i * 256;
            int n  = id >> 2;
            int kq = (id & 3) * 4;
            int j  = bn + n;
            float4 v = make_float4(0.f, 0.f, 0.f, 0.f);
            if (j < G3) v = *(const float4*)&Wih[(size_t)j * IN + k0 + kq];
            Bs[kq + 0][n] = v.x; Bs[kq + 1][n] = v.y;
            Bs[kq + 2][n] = v.z; Bs[kq + 3][n] = v.w;
        }
        __syncthreads();
#pragma unroll
        for (int kk = 0; kk < BKK; kk++) {
            float a[8], b[8];
#pragma unroll
            for (int u = 0; u < 4; u++) {
                a[u]     = As[kk][ty * 4 + u];
                a[4 + u] = As[kk][64 + ty * 4 + u];
                b[u]     = Bs[kk][tx * 4 + u];
                b[4 + u] = Bs[kk][64 + tx * 4 + u];
            }
#pragma unroll
            for (int r = 0; r < 8; r++)
#pragma unroll
                for (int c = 0; c < 8; c++) acc[r][c] += a[r] * b[c];
        }
        __syncthreads();
    }
#pragma unroll
    for (int r = 0; r < 8; r++) {
        int m = bm + ((r < 4) ? (ty * 4 + r) : (64 + ty * 4 + (r - 4)));
#pragma unroll
        for (int c = 0; c < 8; c++) {
            int j = bn + ((c < 4) ? (tx * 4 + c) : (64 + tx * 4 + (c - 4)));
            if (j < G3)
                d_gx[(size_t)m * G3 + j] = acc[r][c] + __ldg(&bih[j]);
        }
    }
}

// ------------------- phase body: one chain-step of chain c at phase p -----
__device__ __forceinline__ void gru_phase(
    int p, int c, int i, int tid, int lane,
    const float* wr, const float* wz, const float* wn,
    float bhr, float bhz, float bhn,
    float& pg0, float& pg1, float& pg2,
    float* s_h, float* __restrict__ out)
{
    // lane 0: consume this phase's gates, prefetch this chain's next step
    // (p+2, handled by this same group) — issued before the poll.
    float g0 = 0.f, g1 = 0.f, g2 = 0.f;
    if (lane == 0) {
        g0 = pg0; g1 = pg1; g2 = pg2;
        int sn = p + 2;
        if (sn < T) {
            int row = c ? (sn + 1023 - 2 * (sn & 1023)) : sn;
            const float* gp = &d_gx[(size_t)row * G3];
            pg0 = __ldcg(gp + i);
            pg1 = __ldcg(gp + HID + i);
            pg2 = __ldcg(gp + 2 * HID + i);
        }
    }

    // wait for h_c(p): produced by the other group during our previous phase
    unsigned* cnt = &d_count[c][0];
    if (tid == 0 && p > 0) {
        unsigned tgt = (unsigned)p * GBLK;
        while (ld_rlx(cnt) < tgt) { }
        fence_ar_gpu();
    }
    __syncthreads();

    // stage h_c(p) into SMEM (160 float4)
    if (tid < H4) {
        const float4* h4 = (const float4*)d_h[c][p & 1];
        ((float4*)s_h)[tid] = __ldcg(&h4[tid]);
    }
    __syncthreads();

    // dot products from SMEM
    float a = 0.f, z = 0.f, n = 0.f;
#pragma unroll
    for (int cc = 0; cc < 5; cc++) {
        float4 hv = *(const float4*)&s_h[cc * 128 + lane * 4];
        const float* WR = &wr[cc * 4];
        const float* WZ = &wz[cc * 4];
        const float* WN = &wn[cc * 4];
        a += WR[0] * hv.x + WR[1] * hv.y + WR[2] * hv.z + WR[3] * hv.w;
        z += WZ[0] * hv.x + WZ[1] * hv.y + WZ[2] * hv.z + WZ[3] * hv.w;
        n += WN[0] * hv.x + WN[1] * hv.y + WN[2] * hv.z + WN[3] * hv.w;
    }
#pragma unroll
    for (int o = 16; o; o >>= 1) {
        a += __shfl_down_sync(0xffffffffu, a, o);
        z += __shfl_down_sync(0xffffffffu, z, o);
        n += __shfl_down_sync(0xffffffffu, n, o);
    }

    if (lane == 0) {
        float hi = s_h[i];
        float r_ = sigm(g0 + a + bhr);
        float z_ = sigm(g1 + z + bhz);
        float n_ = tanh_fast(g2 + r_ * (n + bhn));
        float hn = (1.0f - z_) * n_ + z_ * hi;
        d_h[c][(p + 1) & 1][i] = hn;
        if (p == T - 1) out[c * HID + i] = hn;
    }

    __syncthreads();                  // all warps done with s_h + h stores
    if (tid == 0) red_rel_add(cnt, 1u);   // release arrival (fire-and-forget)
}

// ------------------- kernel 3: interleaved dual-chain GRU recurrence ------
// Group 0 = blocks [0,60), group 1 = blocks [60,120). Each group covers all
// 600 hidden indices. Phase p: group g computes chain c = (p&1)^g, step p.
// Each group consumes the other group's previous-phase output, so one
// chain's publish->observe latency hides under the other chain's compute.
__global__ void __launch_bounds__(RTHREADS, 1)
gru_recur(const float* __restrict__ Whh,
          const float* __restrict__ bhh,
          float* __restrict__ out) {
    __shared__ __align__(16) float s_h[640];

    int tid  = threadIdx.x;
    int w    = tid >> 5;
    int lane = tid & 31;
    int g    = (blockIdx.x < GBLK) ? 0 : 1;     // group
    int blkl = blockIdx.x - g * GBLK;
    int i    = blkl * IPB + w;                  // this warp's hidden index
    int cE   = g;                               // chain on even phases
    int cO   = 1 - g;                           // chain on odd phases

    // --- load this warp's W_hh rows into registers (zero-padded) ---
    float wr[20], wz[20], wn[20];
#pragma unroll
    for (int c = 0; c < 5; c++) {
#pragma unroll
        for (int u = 0; u < 4; u++) {
            int k = c * 128 + lane * 4 + u;
            bool ok = (k < HID);
            wr[c * 4 + u] = ok ? Whh[(size_t)(0 * HID + i) * HID + k] : 0.0f;
            wz[c * 4 + u] = ok ? Whh[(size_t)(1 * HID + i) * HID + k] : 0.0f;
            wn[c * 4 + u] = ok ? Whh[(size_t)(2 * HID + i) * HID + k] : 0.0f;
        }
    }
    float bhr = 0.f, bhz = 0.f, bhn = 0.f;
    if (lane == 0) {
        bhr = bhh[i];
        bhz = bhh[HID + i];
        bhn = bhh[2 * HID + i];
    }

    // --- initial gx prefetch: even-chain step 0, odd-chain step 1 ---
    float pgE0 = 0.f, pgE1 = 0.f, pgE2 = 0.f;
    float pgO0 = 0.f, pgO1 = 0.f, pgO2 = 0.f;
    if (lane == 0) {
        int rowE = cE ? 1023 : 0;                 // chain cE, step 0
        int rowO = cO ? 1022 : 1;                 // chain cO, step 1
        const float* gE = &d_gx[(size_t)rowE * G3];
        const float* gO = &d_gx[(size_t)rowO * G3];
        pgE0 = __ldcg(gE + i); pgE1 = __ldcg(gE + HID + i); pgE2 = __ldcg(gE + 2 * HID + i);
        pgO0 = __ldcg(gO + i); pgO1 = __ldcg(gO + HID + i); pgO2 = __ldcg(gO + 2 * HID + i);
    }

    for (int p = 0; p < T; p += 2) {
        gru_phase(p,     cE, i, tid, lane, wr, wz, wn, bhr, bhz, bhn,
                  pgE0, pgE1, pgE2, s_h, out);
        gru_phase(p + 1, cO, i, tid, lane, wr, wz, wn, bhr, bhz, bhn,
                  pgO0, pgO1, pgO2, s_h, out);
    }
}

// ------------------- launch ------------------------------------------------
extern "C" void kernel_launch(void* const* d_in, const int* in_sizes, int n_in,
                              void* d_out, int out_size) {
    const float* context = (const float*)d_in[0];   // [16,1024,509]
    const int*   tags    = (const int*)  d_in[1];   // [16,1024]
    const float* tag_emb = (const float*)d_in[2];   // [3,3]
    const float* W_ih    = (const float*)d_in[3];   // [1800,512]
    const float* W_hh    = (const float*)d_in[4];   // [1800,600]
    const float* b_ih    = (const float*)d_in[5];   // [1800]
    const float* b_hh    = (const float*)d_in[6];   // [1800]
    float*       out     = (float*)d_out;           // [1200]

    init_bufs<<<4, 640>>>();
    build_x<<<T, IN>>>(context, tags, tag_emb);
    dim3 g((T + BM - 1) / BM, (G3 + BN - 1) / BN);  // 128 x 15
    gemm_gx<<<g, 256>>>(W_ih, b_ih);
    gru_recur<<<NBLK, RTHREADS>>>(W_hh, b_hh, out);
}